// round 7
// baseline (speedup 1.0000x reference)
#include <cuda_runtime.h>

#define SQ   1024
#define BS   64
#define HD   512
#define ED   256
#define VB   32000
#define G3   1536
#define EOSV 2
#define NEOS 32

#define NBG  4            // batch groups (16 rows each)
#define NRG  32           // j groups (16 h-dims each)
#define NCTA (NBG*NRG)    // 128 persistent CTAs

// gru shared memory layout (floats)
#define SM_H      (16*HD)          // 8192   h tile
#define SM_PSUM   (48*256)         // 12288  slot-major partials [g*16+slot][b*16+jl]
#define SM_GIBUF  (2*256*3)        // 1536   double-buffered gi staging
#define SM_DEST   (2*16)           // 32     (as float slots, used as int)
#define GRU_SMEM  ((SM_H + SM_PSUM + SM_GIBUF + SM_DEST) * 4)

typedef unsigned long long u64;

// ------------------- device scratch (static only; no allocs) ----------------
__device__ float    g_Gtab[(size_t)VB * G3];   // ~197MB input-projection table
__device__ float    g_h[2][BS * HD];           // double-buffered hidden state
__device__ int      g_dest[SQ * BS];           // EOS compaction slot or -1
__device__ unsigned g_ctr[NBG * 64];           // barrier counters, 256B stride

// ------------------- packed f32x2 helpers ----------------------------------
__device__ __forceinline__ u64 ffma2(u64 a, u64 b, u64 c) {
    u64 d;
    asm("fma.rn.f32x2 %0, %1, %2, %3;" : "=l"(d) : "l"(a), "l"(b), "l"(c));
    return d;
}
__device__ __forceinline__ float2 unpack2(u64 v) {
    float2 f;
    asm("mov.b64 {%0, %1}, %2;" : "=f"(f.x), "=f"(f.y) : "l"(v));
    return f;
}
__device__ __forceinline__ float hsum2(u64 v) {
    float2 f = unpack2(v);
    return f.x + f.y;
}
__device__ __forceinline__ u64 bcast2(float x) {
    u64 d;
    asm("mov.b64 %0, {%1, %1};" : "=l"(d) : "f"(x));
    return d;
}
__device__ __forceinline__ unsigned ld_acq(const unsigned* p) {
    unsigned v;
    asm volatile("ld.acquire.gpu.global.u32 %0, [%1];" : "=r"(v) : "l"(p));
    return v;
}
__device__ __forceinline__ void red_release_add(unsigned* p, unsigned v) {
    asm volatile("red.release.gpu.global.add.u32 [%0], %1;" :: "l"(p), "r"(v) : "memory");
}

// ------------------- Gtab GEMM (+fused prep): G = w_ih * emb^T + b_ih ------
__global__ void __launch_bounds__(256) gtab_kernel(
    const float* __restrict__ emb,
    const float* __restrict__ w_ih,
    const float* __restrict__ b_ih,
    const int*   __restrict__ tokens)
{
    // ---- fused prep: h0, counters, EOS scan (first 64 flat CTAs, warp 0) ----
    int fid = blockIdx.y * 12 + blockIdx.x;
    if (fid < BS && threadIdx.x < 32) {
        int b = fid, t = threadIdx.x;
        if (fid == 0 && t < NBG) g_ctr[t * 64] = 0u;
        for (int i = t; i < HD; i += 32) g_h[0][b * HD + i] = 0.f;
        int s0 = t * 32;
        int cnt = 0;
        #pragma unroll
        for (int i = 0; i < 32; i++) cnt += (tokens[b * SQ + s0 + i] == EOSV);
        int pre = cnt;
        #pragma unroll
        for (int m = 1; m < 32; m <<= 1) {
            int v = __shfl_up_sync(0xffffffffu, pre, m);
            if (t >= m) pre += v;
        }
        pre -= cnt;
        int k = pre;
        #pragma unroll
        for (int i = 0; i < 32; i++) {
            int s = s0 + i;
            bool e = (tokens[b * SQ + s] == EOSV);
            g_dest[s * BS + b] = (e && k < NEOS) ? k : -1;
            k += e;
        }
    }

    // ---- GEMM: 128x128 tile, 16-k steps, 8x8 microtile, f32x2 ----
    __shared__ float A_sT[16 * 132];
    __shared__ float B_sT[16 * 132];

    int tid = threadIdx.x;
    int tx = tid & 15, ty = tid >> 4;
    int g0 = blockIdx.x * 128;
    int t0 = blockIdx.y * 128;

    u64 acc[8][4];
    #pragma unroll
    for (int i = 0; i < 8; i++)
        #pragma unroll
        for (int j = 0; j < 4; j++) acc[i][j] = 0ull;

    for (int k0 = 0; k0 < ED; k0 += 16) {
        __syncthreads();
        #pragma unroll
        for (int i = 0; i < 2; i++) {
            int ff  = tid + i * 256;
            int row = ff >> 2;
            int c4  = (ff & 3) * 4;
            float4 va = *(const float4*)&emb[(size_t)(t0 + row) * ED + k0 + c4];
            A_sT[(c4 + 0) * 132 + row] = va.x;
            A_sT[(c4 + 1) * 132 + row] = va.y;
            A_sT[(c4 + 2) * 132 + row] = va.z;
            A_sT[(c4 + 3) * 132 + row] = va.w;
            float4 vb = *(const float4*)&w_ih[(size_t)(g0 + row) * ED + k0 + c4];
            B_sT[(c4 + 0) * 132 + row] = vb.x;
            B_sT[(c4 + 1) * 132 + row] = vb.y;
            B_sT[(c4 + 2) * 132 + row] = vb.z;
            B_sT[(c4 + 3) * 132 + row] = vb.w;
        }
        __syncthreads();
        #pragma unroll
        for (int k = 0; k < 16; k++) {
            float4 a0 = *(const float4*)&A_sT[k * 132 + ty * 4];
            float4 a1 = *(const float4*)&A_sT[k * 132 + 64 + ty * 4];
            u64 b0x = *(const u64*)&B_sT[k * 132 + tx * 4];
            u64 b0y = *(const u64*)&B_sT[k * 132 + tx * 4 + 2];
            u64 b1x = *(const u64*)&B_sT[k * 132 + 64 + tx * 4];
            u64 b1y = *(const u64*)&B_sT[k * 132 + 64 + tx * 4 + 2];
            float af[8] = {a0.x, a0.y, a0.z, a0.w, a1.x, a1.y, a1.z, a1.w};
            #pragma unroll
            for (int i = 0; i < 8; i++) {
                u64 ap = bcast2(af[i]);
                acc[i][0] = ffma2(ap, b0x, acc[i][0]);
                acc[i][1] = ffma2(ap, b0y, acc[i][1]);
                acc[i][2] = ffma2(ap, b1x, acc[i][2]);
                acc[i][3] = ffma2(ap, b1y, acc[i][3]);
            }
        }
    }

    float4 bia0 = *(const float4*)&b_ih[g0 + tx * 4];
    float4 bia1 = *(const float4*)&b_ih[g0 + 64 + tx * 4];
    #pragma unroll
    for (int i = 0; i < 8; i++) {
        int trow = t0 + (i >> 2) * 64 + ty * 4 + (i & 3);
        float2 c0 = unpack2(acc[i][0]);
        float2 c1 = unpack2(acc[i][1]);
        float2 c2 = unpack2(acc[i][2]);
        float2 c3 = unpack2(acc[i][3]);
        float4 o0 = make_float4(c0.x + bia0.x, c0.y + bia0.y, c1.x + bia0.z, c1.y + bia0.w);
        float4 o1 = make_float4(c2.x + bia1.x, c2.y + bia1.y, c3.x + bia1.z, c3.y + bia1.w);
        *(float4*)&g_Gtab[(size_t)trow * G3 + g0 + tx * 4]      = o0;
        *(float4*)&g_Gtab[(size_t)trow * G3 + g0 + 64 + tx * 4] = o1;
    }
}

// ------------------- persistent GRU recurrence ------------------------------
// 512 threads/CTA (16 warps = 4/SMSP).  ks = tid>>4 (0..31, 16-elem K-slice),
// jl = tid&15 (broadcast lanes). W_hh slice in 24 u64 regs.
// psum slot-major [48][256]: conflict-free stores AND loads.
// Role-split tail: lower 256 threads phase 2 while upper 256 prefetch gi(s+1).
// Barrier = all-thread acquire poll.
__global__ void __launch_bounds__(512, 1) gru_kernel(
    const int*   __restrict__ tokens,
    const float* __restrict__ w_hh,
    const float* __restrict__ b_hh,
    float*       __restrict__ out)
{
    extern __shared__ float sm[];
    float (*h_s)[HD] = (float(*)[HD])sm;              // [16][512]
    float* psum  = sm + SM_H;                          // [48][256]
    float* gibuf = sm + SM_H + SM_PSUM;                // [2][256][3]
    int*   dest_s = (int*)(sm + SM_H + SM_PSUM + SM_GIBUF);  // [2][16]

    int tid = threadIdx.x;
    int bg = blockIdx.x & 3, rg = blockIdx.x >> 2;
    int ks = tid >> 4;          // 0..31
    int jl = tid & 15;
    int jG1 = rg * 16 + jl;
    int lane = tid & 31;
    int wslot = tid >> 5;       // warp index == psum slot

    // one-time W_hh register slice: 3 gates x 16 elements
    u64 wr[8], wz[8], wn[8];
    #pragma unroll
    for (int i4 = 0; i4 < 4; i4++) {
        int col = ks * 16 + i4 * 4;
        const float* r0 = &w_hh[(size_t)(0 * HD + jG1) * HD + col];
        const float* r1 = &w_hh[(size_t)(1 * HD + jG1) * HD + col];
        const float* r2 = &w_hh[(size_t)(2 * HD + jG1) * HD + col];
        wr[2 * i4] = *(const u64*)r0;  wr[2 * i4 + 1] = *(const u64*)(r0 + 2);
        wz[2 * i4] = *(const u64*)r1;  wz[2 * i4 + 1] = *(const u64*)(r1 + 2);
        wn[2 * i4] = *(const u64*)r2;  wn[2 * i4 + 1] = *(const u64*)(r2 + 2);
    }

    // lower-half (phase 2) role
    int bl2 = tid >> 4, j2 = tid & 15;        // valid when tid < 256
    int bG2 = bg * 16 + bl2;
    int jG2 = rg * 16 + j2;
    float bhr = 0.f, bhz = 0.f, bhn = 0.f;
    if (tid < 256) {
        bhr = b_hh[jG2];
        bhz = b_hh[HD + jG2];
        bhn = b_hh[2 * HD + jG2];
    }
    // upper-half (prefetch) role
    int ut = tid - 256;
    int ubG = bg * 16 + (ut >> 4);
    int ujG = rg * 16 + (ut & 15);

    // preload gi(0), dest(0) into buffer 0
    if (tid >= 256) {
        int tok0 = __ldg(&tokens[ubG * SQ]);
        const float* gp = &g_Gtab[(size_t)tok0 * G3 + ujG];
        float* gb = &gibuf[(0 * 256 + ut) * 3];
        gb[0] = __ldcs(gp);
        gb[1] = __ldcs(gp + HD);
        gb[2] = __ldcs(gp + 2 * HD);
        if ((ut & 15) == 0) dest_s[ut >> 4] = __ldg(&g_dest[ubG]);
    }
    __syncthreads();

    for (int s = 0; s < SQ; s++) {
        // ---- load h(s): 16 rows x 512 f = 2048 float4 -> 4 per thread ----
        {
            const float* hsrc = &g_h[s & 1][bg * 16 * HD];
            float4 hv[4];
            #pragma unroll
            for (int i = 0; i < 4; i++) {
                int f = tid + i * 512;
                hv[i] = __ldcg((const float4*)&hsrc[(f >> 7) * HD + (f & 127) * 4]);
            }
            #pragma unroll
            for (int i = 0; i < 4; i++) {
                int f = tid + i * 512;
                *(float4*)&h_s[f >> 7][(f & 127) * 4] = hv[i];
            }
        }
        __syncthreads();

        // ---- phase 1: split-K partials, 2 batches per pass (6 chains) ----
        #pragma unroll 2
        for (int p = 0; p < 8; p++) {
            int b0 = 2 * p, b1 = 2 * p + 1;
            const float* hb0 = &h_s[b0][ks * 16];
            const float* hb1 = &h_s[b1][ks * 16];
            u64 a0r = 0, a0z = 0, a0n = 0, a1r = 0, a1z = 0, a1n = 0;
            #pragma unroll
            for (int i4 = 0; i4 < 4; i4++) {
                ulonglong2 h0 = *(const ulonglong2*)&hb0[i4 * 4];
                ulonglong2 h1 = *(const ulonglong2*)&hb1[i4 * 4];
                a0r = ffma2(wr[2 * i4], h0.x, a0r);
                a1r = ffma2(wr[2 * i4], h1.x, a1r);
                a0z = ffma2(wz[2 * i4], h0.x, a0z);
                a1z = ffma2(wz[2 * i4], h1.x, a1z);
                a0n = ffma2(wn[2 * i4], h0.x, a0n);
                a1n = ffma2(wn[2 * i4], h1.x, a1n);
                a0r = ffma2(wr[2 * i4 + 1], h0.y, a0r);
                a1r = ffma2(wr[2 * i4 + 1], h1.y, a1r);
                a0z = ffma2(wz[2 * i4 + 1], h0.y, a0z);
                a1z = ffma2(wz[2 * i4 + 1], h1.y, a1z);
                a0n = ffma2(wn[2 * i4 + 1], h0.y, a0n);
                a1n = ffma2(wn[2 * i4 + 1], h1.y, a1n);
            }
            float v0r = hsum2(a0r), v0z = hsum2(a0z), v0n = hsum2(a0n);
            float v1r = hsum2(a1r), v1z = hsum2(a1z), v1n = hsum2(a1n);
            // combine ks-pair (same jl, lane^16)
            v0r += __shfl_xor_sync(0xffffffffu, v0r, 16);
            v0z += __shfl_xor_sync(0xffffffffu, v0z, 16);
            v0n += __shfl_xor_sync(0xffffffffu, v0n, 16);
            v1r += __shfl_xor_sync(0xffffffffu, v1r, 16);
            v1z += __shfl_xor_sync(0xffffffffu, v1z, 16);
            v1n += __shfl_xor_sync(0xffffffffu, v1n, 16);
            if (lane < 16) {                     // ks even
                psum[(0 * 16 + wslot) * 256 + b0 * 16 + jl] = v0r;
                psum[(1 * 16 + wslot) * 256 + b0 * 16 + jl] = v0z;
                psum[(2 * 16 + wslot) * 256 + b0 * 16 + jl] = v0n;
                psum[(0 * 16 + wslot) * 256 + b1 * 16 + jl] = v1r;
                psum[(1 * 16 + wslot) * 256 + b1 * 16 + jl] = v1z;
                psum[(2 * 16 + wslot) * 256 + b1 * 16 + jl] = v1n;
            }
        }

        // ---- upper half: prefetch gi(s+1)/dest(s+1) into staging buffer ----
        if (tid >= 256 && s + 1 < SQ) {
            int tk = __ldg(&tokens[ubG * SQ + s + 1]);
            const float* gq = &g_Gtab[(size_t)tk * G3 + ujG];
            float* gb = &gibuf[(((s + 1) & 1) * 256 + ut) * 3];
            gb[0] = __ldcs(gq);
            gb[1] = __ldcs(gq + HD);
            gb[2] = __ldcs(gq + 2 * HD);
            if ((ut & 15) == 0)
                dest_s[((s + 1) & 1) * 16 + (ut >> 4)] = __ldg(&g_dest[(s + 1) * BS + ubG]);
        }
        __syncthreads();

        // ---- phase 2 (lower half): reduce 16 slots/gate, gates, store ----
        if (tid < 256) {
            float t0, t1, t2s, t3;
            // rsum
            t0 = psum[0 * 256 + tid] + psum[1 * 256 + tid];
            t1 = psum[2 * 256 + tid] + psum[3 * 256 + tid];
            t2s = psum[4 * 256 + tid] + psum[5 * 256 + tid];
            t3 = psum[6 * 256 + tid] + psum[7 * 256 + tid];
            float r0 = (t0 + t1) + (t2s + t3);
            t0 = psum[8 * 256 + tid] + psum[9 * 256 + tid];
            t1 = psum[10 * 256 + tid] + psum[11 * 256 + tid];
            t2s = psum[12 * 256 + tid] + psum[13 * 256 + tid];
            t3 = psum[14 * 256 + tid] + psum[15 * 256 + tid];
            float rsum = r0 + ((t0 + t1) + (t2s + t3));
            // zsum
            t0 = psum[16 * 256 + tid] + psum[17 * 256 + tid];
            t1 = psum[18 * 256 + tid] + psum[19 * 256 + tid];
            t2s = psum[20 * 256 + tid] + psum[21 * 256 + tid];
            t3 = psum[22 * 256 + tid] + psum[23 * 256 + tid];
            float z0 = (t0 + t1) + (t2s + t3);
            t0 = psum[24 * 256 + tid] + psum[25 * 256 + tid];
            t1 = psum[26 * 256 + tid] + psum[27 * 256 + tid];
            t2s = psum[28 * 256 + tid] + psum[29 * 256 + tid];
            t3 = psum[30 * 256 + tid] + psum[31 * 256 + tid];
            float zsum = z0 + ((t0 + t1) + (t2s + t3));
            // nsum
            t0 = psum[32 * 256 + tid] + psum[33 * 256 + tid];
            t1 = psum[34 * 256 + tid] + psum[35 * 256 + tid];
            t2s = psum[36 * 256 + tid] + psum[37 * 256 + tid];
            t3 = psum[38 * 256 + tid] + psum[39 * 256 + tid];
            float n0 = (t0 + t1) + (t2s + t3);
            t0 = psum[40 * 256 + tid] + psum[41 * 256 + tid];
            t1 = psum[42 * 256 + tid] + psum[43 * 256 + tid];
            t2s = psum[44 * 256 + tid] + psum[45 * 256 + tid];
            t3 = psum[46 * 256 + tid] + psum[47 * 256 + tid];
            float nsum = n0 + ((t0 + t1) + (t2s + t3));

            const float* gb = &gibuf[((s & 1) * 256 + tid) * 3];
            float pr = gb[0], pz = gb[1], pn = gb[2];
            int   pd = dest_s[(s & 1) * 16 + bl2];
            float hprev = h_s[bl2][jG2];

            float r  = 1.f / (1.f + __expf(-(pr + rsum + bhr)));
            float z  = 1.f / (1.f + __expf(-(pz + zsum + bhz)));
            float nx = pn + r * (nsum + bhn);
            float e2 = __expf(-2.f * nx);
            float n  = 2.f / (1.f + e2) - 1.f;          // tanh, inf-safe
            float hnew = fmaf(z, hprev - n, n);         // (1-z)*n + z*h

            g_h[(s + 1) & 1][bG2 * HD + jG2] = hnew;
            if (pd >= 0) out[((size_t)pd * BS + bG2) * HD + jG2] = hnew;
        }

        // ---- per-batch-group barrier (32 CTAs), skipped on last step ----
        if (s + 1 < SQ) {
            __syncthreads();                    // orders h stores before release
            if (tid == 0) red_release_add(&g_ctr[bg * 64], 1u);
            unsigned tgt = 32u * (unsigned)(s + 1);
            while (ld_acq(&g_ctr[bg * 64]) < tgt) { }
        }
    }
}

// ------------------- launch -------------------------------------------------
extern "C" void kernel_launch(void* const* d_in, const int* in_sizes, int n_in,
                              void* d_out, int out_size) {
    const int*   tokens = (const int*)d_in[0];
    const float* emb    = (const float*)d_in[1];
    const float* w_ih   = (const float*)d_in[2];
    const float* w_hh   = (const float*)d_in[3];
    const float* b_ih   = (const float*)d_in[4];
    const float* b_hh   = (const float*)d_in[5];
    float* out = (float*)d_out;

    cudaFuncSetAttribute(gru_kernel,
                         cudaFuncAttributeMaxDynamicSharedMemorySize, GRU_SMEM);

    gtab_kernel<<<dim3(G3 / 128, VB / 128), 256>>>(emb, w_ih, b_ih, tokens);
    gru_kernel<<<NCTA, 512, GRU_SMEM>>>(tokens, w_hh, b_hh, out);
}

// round 8
// speedup vs baseline: 1.0085x; 1.0085x over previous
#include <cuda_runtime.h>

#define SQ   1024
#define BS   64
#define HD   512
#define ED   256
#define VB   32000
#define G3   1536
#define EOSV 2
#define NEOS 32

#define NBG  4            // batch groups (16 rows each)
#define NRG  32           // j groups (16 h-dims each)
#define NCTA (NBG*NRG)    // 128 persistent CTAs

// gru shared memory layout (floats)
#define SM_H      (16*HD)          // 8192   h tile
#define SM_PSUM   (48*256)         // 12288  slot-major partials [g*16+slot][b*16+jl]
#define SM_GIBUF  (2*256*3)        // 1536   double-buffered gi staging
#define SM_DEST   (2*16)           // 32     (as float slots, used as int)
#define GRU_SMEM  ((SM_H + SM_PSUM + SM_GIBUF + SM_DEST) * 4)

typedef unsigned long long u64;

// ------------------- device scratch (static only; no allocs) ----------------
__device__ float    g_Gtab[(size_t)VB * G3];   // ~197MB input-projection table
__device__ float    g_h[2][BS * HD];           // double-buffered hidden state
__device__ int      g_dest[SQ * BS];           // EOS compaction slot or -1
__device__ unsigned g_ctr[NBG * 64];           // barrier counters, 256B stride

// ------------------- packed f32x2 helpers ----------------------------------
__device__ __forceinline__ u64 ffma2(u64 a, u64 b, u64 c) {
    u64 d;
    asm("fma.rn.f32x2 %0, %1, %2, %3;" : "=l"(d) : "l"(a), "l"(b), "l"(c));
    return d;
}
__device__ __forceinline__ float2 unpack2(u64 v) {
    float2 f;
    asm("mov.b64 {%0, %1}, %2;" : "=f"(f.x), "=f"(f.y) : "l"(v));
    return f;
}
__device__ __forceinline__ float hsum2(u64 v) {
    float2 f = unpack2(v);
    return f.x + f.y;
}
__device__ __forceinline__ u64 bcast2(float x) {
    u64 d;
    asm("mov.b64 %0, {%1, %1};" : "=l"(d) : "f"(x));
    return d;
}
__device__ __forceinline__ unsigned ld_acq(const unsigned* p) {
    unsigned v;
    asm volatile("ld.acquire.gpu.global.u32 %0, [%1];" : "=r"(v) : "l"(p));
    return v;
}
__device__ __forceinline__ void red_release_add(unsigned* p, unsigned v) {
    asm volatile("red.release.gpu.global.add.u32 [%0], %1;" :: "l"(p), "r"(v) : "memory");
}

// ------------------- Gtab GEMM (+fused prep): G = w_ih * emb^T + b_ih ------
__global__ void __launch_bounds__(256) gtab_kernel(
    const float* __restrict__ emb,
    const float* __restrict__ w_ih,
    const float* __restrict__ b_ih,
    const int*   __restrict__ tokens)
{
    // ---- fused prep: h0, counters, EOS scan (first 64 flat CTAs, warp 0) ----
    int fid = blockIdx.y * 12 + blockIdx.x;
    if (fid < BS && threadIdx.x < 32) {
        int b = fid, t = threadIdx.x;
        if (fid == 0 && t < NBG) g_ctr[t * 64] = 0u;
        for (int i = t; i < HD; i += 32) g_h[0][b * HD + i] = 0.f;
        int s0 = t * 32;
        int cnt = 0;
        #pragma unroll
        for (int i = 0; i < 32; i++) cnt += (tokens[b * SQ + s0 + i] == EOSV);
        int pre = cnt;
        #pragma unroll
        for (int m = 1; m < 32; m <<= 1) {
            int v = __shfl_up_sync(0xffffffffu, pre, m);
            if (t >= m) pre += v;
        }
        pre -= cnt;
        int k = pre;
        #pragma unroll
        for (int i = 0; i < 32; i++) {
            int s = s0 + i;
            bool e = (tokens[b * SQ + s] == EOSV);
            g_dest[s * BS + b] = (e && k < NEOS) ? k : -1;
            k += e;
        }
    }

    // ---- GEMM: 128x128 tile, 16-k steps, 8x8 microtile, f32x2 ----
    __shared__ float A_sT[16 * 132];
    __shared__ float B_sT[16 * 132];

    int tid = threadIdx.x;
    int tx = tid & 15, ty = tid >> 4;
    int g0 = blockIdx.x * 128;
    int t0 = blockIdx.y * 128;

    u64 acc[8][4];
    #pragma unroll
    for (int i = 0; i < 8; i++)
        #pragma unroll
        for (int j = 0; j < 4; j++) acc[i][j] = 0ull;

    for (int k0 = 0; k0 < ED; k0 += 16) {
        __syncthreads();
        #pragma unroll
        for (int i = 0; i < 2; i++) {
            int ff  = tid + i * 256;
            int row = ff >> 2;
            int c4  = (ff & 3) * 4;
            float4 va = *(const float4*)&emb[(size_t)(t0 + row) * ED + k0 + c4];
            A_sT[(c4 + 0) * 132 + row] = va.x;
            A_sT[(c4 + 1) * 132 + row] = va.y;
            A_sT[(c4 + 2) * 132 + row] = va.z;
            A_sT[(c4 + 3) * 132 + row] = va.w;
            float4 vb = *(const float4*)&w_ih[(size_t)(g0 + row) * ED + k0 + c4];
            B_sT[(c4 + 0) * 132 + row] = vb.x;
            B_sT[(c4 + 1) * 132 + row] = vb.y;
            B_sT[(c4 + 2) * 132 + row] = vb.z;
            B_sT[(c4 + 3) * 132 + row] = vb.w;
        }
        __syncthreads();
        #pragma unroll
        for (int k = 0; k < 16; k++) {
            float4 a0 = *(const float4*)&A_sT[k * 132 + ty * 4];
            float4 a1 = *(const float4*)&A_sT[k * 132 + 64 + ty * 4];
            u64 b0x = *(const u64*)&B_sT[k * 132 + tx * 4];
            u64 b0y = *(const u64*)&B_sT[k * 132 + tx * 4 + 2];
            u64 b1x = *(const u64*)&B_sT[k * 132 + 64 + tx * 4];
            u64 b1y = *(const u64*)&B_sT[k * 132 + 64 + tx * 4 + 2];
            float af[8] = {a0.x, a0.y, a0.z, a0.w, a1.x, a1.y, a1.z, a1.w};
            #pragma unroll
            for (int i = 0; i < 8; i++) {
                u64 ap = bcast2(af[i]);
                acc[i][0] = ffma2(ap, b0x, acc[i][0]);
                acc[i][1] = ffma2(ap, b0y, acc[i][1]);
                acc[i][2] = ffma2(ap, b1x, acc[i][2]);
                acc[i][3] = ffma2(ap, b1y, acc[i][3]);
            }
        }
    }

    float4 bia0 = *(const float4*)&b_ih[g0 + tx * 4];
    float4 bia1 = *(const float4*)&b_ih[g0 + 64 + tx * 4];
    #pragma unroll
    for (int i = 0; i < 8; i++) {
        int trow = t0 + (i >> 2) * 64 + ty * 4 + (i & 3);
        float2 c0 = unpack2(acc[i][0]);
        float2 c1 = unpack2(acc[i][1]);
        float2 c2 = unpack2(acc[i][2]);
        float2 c3 = unpack2(acc[i][3]);
        float4 o0 = make_float4(c0.x + bia0.x, c0.y + bia0.y, c1.x + bia0.z, c1.y + bia0.w);
        float4 o1 = make_float4(c2.x + bia1.x, c2.y + bia1.y, c3.x + bia1.z, c3.y + bia1.w);
        *(float4*)&g_Gtab[(size_t)trow * G3 + g0 + tx * 4]      = o0;
        *(float4*)&g_Gtab[(size_t)trow * G3 + g0 + 64 + tx * 4] = o1;
    }
}

// ------------------- persistent GRU recurrence ------------------------------
// 512 threads/CTA (16 warps = 4/SMSP).  ks = tid>>4 (0..31, 16-elem K-slice),
// jl = tid&15 (broadcast lanes). W_hh slice in 24 u64 regs.
// psum slot-major [48][256]: conflict-free stores AND loads.
// Role-split tail: lower 256 threads phase 2 while upper 256 prefetch gi(s+1).
// Barrier: tid0-only poll (32 pollers per L2 line, NOT 16384) + bar.sync wake.
__global__ void __launch_bounds__(512, 1) gru_kernel(
    const int*   __restrict__ tokens,
    const float* __restrict__ w_hh,
    const float* __restrict__ b_hh,
    float*       __restrict__ out)
{
    extern __shared__ float sm[];
    float (*h_s)[HD] = (float(*)[HD])sm;              // [16][512]
    float* psum  = sm + SM_H;                          // [48][256]
    float* gibuf = sm + SM_H + SM_PSUM;                // [2][256][3]
    int*   dest_s = (int*)(sm + SM_H + SM_PSUM + SM_GIBUF);  // [2][16]

    int tid = threadIdx.x;
    int bg = blockIdx.x & 3, rg = blockIdx.x >> 2;
    int ks = tid >> 4;          // 0..31
    int jl = tid & 15;
    int jG1 = rg * 16 + jl;
    int lane = tid & 31;
    int wslot = tid >> 5;       // warp index == psum slot

    // one-time W_hh register slice: 3 gates x 16 elements
    u64 wr[8], wz[8], wn[8];
    #pragma unroll
    for (int i4 = 0; i4 < 4; i4++) {
        int col = ks * 16 + i4 * 4;
        const float* r0 = &w_hh[(size_t)(0 * HD + jG1) * HD + col];
        const float* r1 = &w_hh[(size_t)(1 * HD + jG1) * HD + col];
        const float* r2 = &w_hh[(size_t)(2 * HD + jG1) * HD + col];
        wr[2 * i4] = *(const u64*)r0;  wr[2 * i4 + 1] = *(const u64*)(r0 + 2);
        wz[2 * i4] = *(const u64*)r1;  wz[2 * i4 + 1] = *(const u64*)(r1 + 2);
        wn[2 * i4] = *(const u64*)r2;  wn[2 * i4 + 1] = *(const u64*)(r2 + 2);
    }

    // lower-half (phase 2) role
    int bl2 = tid >> 4, j2 = tid & 15;        // valid when tid < 256
    int bG2 = bg * 16 + bl2;
    int jG2 = rg * 16 + j2;
    float bhr = 0.f, bhz = 0.f, bhn = 0.f;
    if (tid < 256) {
        bhr = b_hh[jG2];
        bhz = b_hh[HD + jG2];
        bhn = b_hh[2 * HD + jG2];
    }
    // upper-half (prefetch) role
    int ut = tid - 256;
    int ubG = bg * 16 + (ut >> 4);
    int ujG = rg * 16 + (ut & 15);

    // preload gi(0), dest(0) into buffer 0
    if (tid >= 256) {
        int tok0 = __ldg(&tokens[ubG * SQ]);
        const float* gp = &g_Gtab[(size_t)tok0 * G3 + ujG];
        float* gb = &gibuf[(0 * 256 + ut) * 3];
        gb[0] = __ldcs(gp);
        gb[1] = __ldcs(gp + HD);
        gb[2] = __ldcs(gp + 2 * HD);
        if ((ut & 15) == 0) dest_s[ut >> 4] = __ldg(&g_dest[ubG]);
    }
    __syncthreads();

    for (int s = 0; s < SQ; s++) {
        // ---- load h(s): 16 rows x 512 f = 2048 float4 -> 4 per thread ----
        {
            const float* hsrc = &g_h[s & 1][bg * 16 * HD];
            float4 hv[4];
            #pragma unroll
            for (int i = 0; i < 4; i++) {
                int f = tid + i * 512;
                hv[i] = __ldcg((const float4*)&hsrc[(f >> 7) * HD + (f & 127) * 4]);
            }
            #pragma unroll
            for (int i = 0; i < 4; i++) {
                int f = tid + i * 512;
                *(float4*)&h_s[f >> 7][(f & 127) * 4] = hv[i];
            }
        }
        __syncthreads();

        // ---- phase 1: split-K partials, 2 batches per pass (6 chains) ----
        #pragma unroll 2
        for (int p = 0; p < 8; p++) {
            int b0 = 2 * p, b1 = 2 * p + 1;
            const float* hb0 = &h_s[b0][ks * 16];
            const float* hb1 = &h_s[b1][ks * 16];
            u64 a0r = 0, a0z = 0, a0n = 0, a1r = 0, a1z = 0, a1n = 0;
            #pragma unroll
            for (int i4 = 0; i4 < 4; i4++) {
                ulonglong2 h0 = *(const ulonglong2*)&hb0[i4 * 4];
                ulonglong2 h1 = *(const ulonglong2*)&hb1[i4 * 4];
                a0r = ffma2(wr[2 * i4], h0.x, a0r);
                a1r = ffma2(wr[2 * i4], h1.x, a1r);
                a0z = ffma2(wz[2 * i4], h0.x, a0z);
                a1z = ffma2(wz[2 * i4], h1.x, a1z);
                a0n = ffma2(wn[2 * i4], h0.x, a0n);
                a1n = ffma2(wn[2 * i4], h1.x, a1n);
                a0r = ffma2(wr[2 * i4 + 1], h0.y, a0r);
                a1r = ffma2(wr[2 * i4 + 1], h1.y, a1r);
                a0z = ffma2(wz[2 * i4 + 1], h0.y, a0z);
                a1z = ffma2(wz[2 * i4 + 1], h1.y, a1z);
                a0n = ffma2(wn[2 * i4 + 1], h0.y, a0n);
                a1n = ffma2(wn[2 * i4 + 1], h1.y, a1n);
            }
            float v0r = hsum2(a0r), v0z = hsum2(a0z), v0n = hsum2(a0n);
            float v1r = hsum2(a1r), v1z = hsum2(a1z), v1n = hsum2(a1n);
            // combine ks-pair (same jl, lane^16)
            v0r += __shfl_xor_sync(0xffffffffu, v0r, 16);
            v0z += __shfl_xor_sync(0xffffffffu, v0z, 16);
            v0n += __shfl_xor_sync(0xffffffffu, v0n, 16);
            v1r += __shfl_xor_sync(0xffffffffu, v1r, 16);
            v1z += __shfl_xor_sync(0xffffffffu, v1z, 16);
            v1n += __shfl_xor_sync(0xffffffffu, v1n, 16);
            if (lane < 16) {                     // ks even
                psum[(0 * 16 + wslot) * 256 + b0 * 16 + jl] = v0r;
                psum[(1 * 16 + wslot) * 256 + b0 * 16 + jl] = v0z;
                psum[(2 * 16 + wslot) * 256 + b0 * 16 + jl] = v0n;
                psum[(0 * 16 + wslot) * 256 + b1 * 16 + jl] = v1r;
                psum[(1 * 16 + wslot) * 256 + b1 * 16 + jl] = v1z;
                psum[(2 * 16 + wslot) * 256 + b1 * 16 + jl] = v1n;
            }
        }

        // ---- upper half: prefetch gi(s+1)/dest(s+1) into staging buffer ----
        if (tid >= 256 && s + 1 < SQ) {
            int tk = __ldg(&tokens[ubG * SQ + s + 1]);
            const float* gq = &g_Gtab[(size_t)tk * G3 + ujG];
            float* gb = &gibuf[(((s + 1) & 1) * 256 + ut) * 3];
            gb[0] = __ldcs(gq);
            gb[1] = __ldcs(gq + HD);
            gb[2] = __ldcs(gq + 2 * HD);
            if ((ut & 15) == 0)
                dest_s[((s + 1) & 1) * 16 + (ut >> 4)] = __ldg(&g_dest[(s + 1) * BS + ubG]);
        }
        __syncthreads();

        // ---- phase 2 (lower half): reduce 16 slots/gate, gates, store ----
        if (tid < 256) {
            float t0, t1, t2s, t3;
            // rsum
            t0 = psum[0 * 256 + tid] + psum[1 * 256 + tid];
            t1 = psum[2 * 256 + tid] + psum[3 * 256 + tid];
            t2s = psum[4 * 256 + tid] + psum[5 * 256 + tid];
            t3 = psum[6 * 256 + tid] + psum[7 * 256 + tid];
            float r0 = (t0 + t1) + (t2s + t3);
            t0 = psum[8 * 256 + tid] + psum[9 * 256 + tid];
            t1 = psum[10 * 256 + tid] + psum[11 * 256 + tid];
            t2s = psum[12 * 256 + tid] + psum[13 * 256 + tid];
            t3 = psum[14 * 256 + tid] + psum[15 * 256 + tid];
            float rsum = r0 + ((t0 + t1) + (t2s + t3));
            // zsum
            t0 = psum[16 * 256 + tid] + psum[17 * 256 + tid];
            t1 = psum[18 * 256 + tid] + psum[19 * 256 + tid];
            t2s = psum[20 * 256 + tid] + psum[21 * 256 + tid];
            t3 = psum[22 * 256 + tid] + psum[23 * 256 + tid];
            float z0 = (t0 + t1) + (t2s + t3);
            t0 = psum[24 * 256 + tid] + psum[25 * 256 + tid];
            t1 = psum[26 * 256 + tid] + psum[27 * 256 + tid];
            t2s = psum[28 * 256 + tid] + psum[29 * 256 + tid];
            t3 = psum[30 * 256 + tid] + psum[31 * 256 + tid];
            float zsum = z0 + ((t0 + t1) + (t2s + t3));
            // nsum
            t0 = psum[32 * 256 + tid] + psum[33 * 256 + tid];
            t1 = psum[34 * 256 + tid] + psum[35 * 256 + tid];
            t2s = psum[36 * 256 + tid] + psum[37 * 256 + tid];
            t3 = psum[38 * 256 + tid] + psum[39 * 256 + tid];
            float n0 = (t0 + t1) + (t2s + t3);
            t0 = psum[40 * 256 + tid] + psum[41 * 256 + tid];
            t1 = psum[42 * 256 + tid] + psum[43 * 256 + tid];
            t2s = psum[44 * 256 + tid] + psum[45 * 256 + tid];
            t3 = psum[46 * 256 + tid] + psum[47 * 256 + tid];
            float nsum = n0 + ((t0 + t1) + (t2s + t3));

            const float* gb = &gibuf[((s & 1) * 256 + tid) * 3];
            float pr = gb[0], pz = gb[1], pn = gb[2];
            int   pd = dest_s[(s & 1) * 16 + bl2];
            float hprev = h_s[bl2][jG2];

            float r  = 1.f / (1.f + __expf(-(pr + rsum + bhr)));
            float z  = 1.f / (1.f + __expf(-(pz + zsum + bhz)));
            float nx = pn + r * (nsum + bhn);
            float e2 = __expf(-2.f * nx);
            float n  = 2.f / (1.f + e2) - 1.f;          // tanh, inf-safe
            float hnew = fmaf(z, hprev - n, n);         // (1-z)*n + z*h

            g_h[(s + 1) & 1][bG2 * HD + jG2] = hnew;
            if (pd >= 0) out[((size_t)pd * BS + bG2) * HD + jG2] = hnew;
        }

        // ---- per-batch-group barrier (32 CTAs), tid0-only poll ----
        if (s + 1 < SQ) {
            __syncthreads();                    // orders h stores before release
            if (tid == 0) {
                red_release_add(&g_ctr[bg * 64], 1u);
                unsigned tgt = 32u * (unsigned)(s + 1);
                while (ld_acq(&g_ctr[bg * 64]) < tgt) { }
            }
            __syncthreads();                    // wake: one poller per CTA
        }
    }
}

// ------------------- launch -------------------------------------------------
extern "C" void kernel_launch(void* const* d_in, const int* in_sizes, int n_in,
                              void* d_out, int out_size) {
    const int*   tokens = (const int*)d_in[0];
    const float* emb    = (const float*)d_in[1];
    const float* w_ih   = (const float*)d_in[2];
    const float* w_hh   = (const float*)d_in[3];
    const float* b_ih   = (const float*)d_in[4];
    const float* b_hh   = (const float*)d_in[5];
    float* out = (float*)d_out;

    cudaFuncSetAttribute(gru_kernel,
                         cudaFuncAttributeMaxDynamicSharedMemorySize, GRU_SMEM);

    gtab_kernel<<<dim3(G3 / 128, VB / 128), 256>>>(emb, w_ih, b_ih, tokens);
    gru_kernel<<<NCTA, 512, GRU_SMEM>>>(tokens, w_hh, b_hh, out);
}